// round 17
// baseline (speedup 1.0000x reference)
#include <cuda_runtime.h>
#include <cuda_fp16.h>
#include <cstdint>
#include <cstddef>

#define D_MODEL 1024
#define NH      16
#define DH      64
#define BB      4
#define TT      2048
#define BT      (BB * TT)

__device__ __half g_qkv[(size_t)BT * 3 * D_MODEL];   // [B*T, 3072]
__device__ __half g_y  [(size_t)BT * D_MODEL];       // [B*T, 1024]
__device__ __half g_x  [(size_t)BT * D_MODEL];       // fp16 copy of x
__device__ __half g_wq [(size_t)3 * D_MODEL * D_MODEL];
__device__ __half g_wp [(size_t)D_MODEL * D_MODEL];

// ---------------------------------------------------------------------------
__device__ __forceinline__ uint32_t pk(float a, float b) {
    __half2 h = __floats2half2_rn(a, b);
    return *(uint32_t*)&h;
}

__device__ __forceinline__ void mma_fp16(float c[4], const uint32_t a[4],
                                         const uint32_t b[2]) {
    asm volatile(
        "mma.sync.aligned.m16n8k16.row.col.f32.f16.f16.f32 "
        "{%0,%1,%2,%3},{%4,%5,%6,%7},{%8,%9},{%0,%1,%2,%3};"
        : "+f"(c[0]), "+f"(c[1]), "+f"(c[2]), "+f"(c[3])
        : "r"(a[0]), "r"(a[1]), "r"(a[2]), "r"(a[3]), "r"(b[0]), "r"(b[1]));
}

__device__ __forceinline__ uint32_t smem_u32(const void* p) {
    uint32_t a;
    asm("{ .reg .u64 t; cvta.to.shared.u64 t, %1; cvt.u32.u64 %0, t; }"
        : "=r"(a) : "l"(p));
    return a;
}

__device__ __forceinline__ void cpa8(uint32_t dst, const void* src) {
    asm volatile("cp.async.ca.shared.global [%0], [%1], 8;"
                 :: "r"(dst), "l"(src) : "memory");
}

// ---------------------------------------------------------------------------
__global__ __launch_bounds__(256)
void f2h(const float* __restrict__ src, __half* __restrict__ dst) {
    int i = (blockIdx.x * 256 + threadIdx.x) * 4;
    float4 v = *(const float4*)&src[i];
    *(uint2*)&dst[i] = make_uint2(pk(v.x, v.y), pk(v.z, v.w));
}

// ---------------------------------------------------------------------------
// FP16 GEMM v4: 3-stage cp.async pipeline (chunk c+2 in flight during
// compute c), single __syncthreads per chunk. 128x128 block, 8 warps,
// K-chunk 32, fragment-order swizzled smem (validated layout).
// Smem: 3 x (A 8KB + B 8KB) = 48KB static (exactly the limit).
// ---------------------------------------------------------------------------
template<typename CT>
__global__ __launch_bounds__(256, 2)
void gemm_fp16(const __half* __restrict__ A, const __half* __restrict__ Bw,
               CT* __restrict__ C, int M, int N, int K) {
    __shared__ __align__(16) uint32_t As[3][8 * 2 * 4 * 32];   // 3 x 2048 words
    __shared__ __align__(16) uint32_t Bs[3][16 * 2 * 2 * 32];  // 3 x 2048 words

    const int tid    = threadIdx.x;
    const int lane   = tid & 31;
    const int wid    = tid >> 5;
    const int warp_m = wid >> 2;
    const int warp_n = wid & 3;
    const int m0     = blockIdx.y * 128;
    const int n0     = blockIdx.x * 128;
    const int g      = lane >> 2;
    const int t      = lane & 3;

    // hoisted per-thread staging coords (invariant across chunks)
    uint32_t dstA[4], dstB[4];
    const __half* srcA[4];
    const __half* srcB[4];
    {
        const uint32_t aBase = smem_u32(As);
        const uint32_t bBase = smem_u32(Bs);
        #pragma unroll
        for (int it = 0; it < 4; it++) {
            int lin = tid + it * 256;
            int row = lin >> 3;
            int q   = lin & 7;
            int pos0 = ((4 * (row & 7) + 2 * (q & 1))) ^ (4 * q);
            int planeA = ((row >> 4) * 2 + (q >> 2)) * 4 + ((row >> 3) & 1) + 2 * ((q >> 1) & 1);
            int planeB = ((row >> 3) * 2 + (q >> 2)) * 2 + ((q >> 1) & 1);
            dstA[it] = aBase + (planeA * 32 + pos0) * 4;
            dstB[it] = bBase + (planeB * 32 + pos0) * 4;
            srcA[it] = &A[(size_t)(m0 + row) * K + q * 4];
            srcB[it] = &Bw[(size_t)(n0 + row) * K + q * 4];
        }
    }

    float acc[4][4][4];
    #pragma unroll
    for (int i = 0; i < 4; i++)
        #pragma unroll
        for (int j = 0; j < 4; j++)
            #pragma unroll
            for (int r = 0; r < 4; r++) acc[i][j][r] = 0.f;

    const int NCH = K / 32;   // >= 32 for these shapes

    // ---- prologue: stage chunks 0 and 1 ----
    #pragma unroll
    for (int it = 0; it < 4; it++) {
        cpa8(dstA[it], srcA[it]);
        cpa8(dstB[it], srcB[it]);
    }
    asm volatile("cp.async.commit_group;" ::: "memory");
    #pragma unroll
    for (int it = 0; it < 4; it++) {
        cpa8(dstA[it] + 8192, srcA[it] + 32);
        cpa8(dstB[it] + 8192, srcB[it] + 32);
    }
    asm volatile("cp.async.commit_group;" ::: "memory");

    int slot = 0;           // slot of chunk c (c % 3)
    int slot2 = 2;          // slot of chunk c+2
    for (int c = 0; c < NCH; c++) {
        if (c < NCH - 1) {
            asm volatile("cp.async.wait_group 1;" ::: "memory");
        } else {
            asm volatile("cp.async.wait_group 0;" ::: "memory");
        }
        __syncthreads();    // chunk c visible to all; compute(c-1) done by all

        if (c + 2 < NCH) {
            const uint32_t nb = slot2 * 8192u;
            const int koff = (c + 2) * 32;
            #pragma unroll
            for (int it = 0; it < 4; it++) {
                cpa8(dstA[it] + nb, srcA[it] + koff);
                cpa8(dstB[it] + nb, srcB[it] + koff);
            }
            asm volatile("cp.async.commit_group;" ::: "memory");
        }

        const uint32_t* Ab = As[slot];
        const uint32_t* Bb = Bs[slot];
        #pragma unroll
        for (int ks = 0; ks < 2; ks++) {
            const int posLo = (4 * g + t) ^ (4 * (4 * ks + ((t >> 1) & 1)));
            const int posHi = (4 * g + t) ^ (4 * (4 * ks + 2 + ((t >> 1) & 1)));
            uint32_t af[4][4], bf[4][2];
            #pragma unroll
            for (int i = 0; i < 4; i++) {
                int base = (((warp_m * 4 + i) * 2 + ks) * 4) * 32;
                af[i][0] = Ab[base + posLo];
                af[i][1] = Ab[base + 32 + posLo];
                af[i][2] = Ab[base + 64 + posHi];
                af[i][3] = Ab[base + 96 + posHi];
            }
            #pragma unroll
            for (int j = 0; j < 4; j++) {
                int base = (((warp_n * 4 + j) * 2 + ks) * 2) * 32;
                bf[j][0] = Bb[base + posLo];
                bf[j][1] = Bb[base + 32 + posHi];
            }
            #pragma unroll
            for (int i = 0; i < 4; i++)
                #pragma unroll
                for (int j = 0; j < 4; j++)
                    mma_fp16(acc[i][j], af[i], bf[j]);
        }

        slot  = (slot == 2)  ? 0 : slot + 1;
        slot2 = (slot2 == 2) ? 0 : slot2 + 1;
    }

    #pragma unroll
    for (int i = 0; i < 4; i++) {
        int rbase = m0 + warp_m * 64 + i * 16 + g;
        #pragma unroll
        for (int j = 0; j < 4; j++) {
            int cbase = n0 + warp_n * 32 + j * 8 + t * 2;
            if constexpr (sizeof(CT) == 2) {
                *(uint32_t*)&C[(size_t)rbase * N + cbase] =
                    pk(acc[i][j][0], acc[i][j][1]);
                *(uint32_t*)&C[(size_t)(rbase + 8) * N + cbase] =
                    pk(acc[i][j][2], acc[i][j][3]);
            } else {
                *(float2*)&C[(size_t)rbase * N + cbase] =
                    make_float2(acc[i][j][0], acc[i][j][1]);
                *(float2*)&C[(size_t)(rbase + 8) * N + cbase] =
                    make_float2(acc[i][j][2], acc[i][j][3]);
            }
        }
    }
}

// ---------------------------------------------------------------------------
// FP16 tensor-core flash attention (round-13 validated, unchanged).
// ---------------------------------------------------------------------------
__global__ __launch_bounds__(128)
void attn_fp16() {
    __shared__ __align__(16) uint32_t Ks[8 * 4 * 2 * 32];   // 8 KB
    __shared__ __align__(16) uint32_t Vs[32 * 64];          // 8 KB

    const int tid  = threadIdx.x;
    const int lane = tid & 31;
    const int w    = tid >> 5;
    const int g    = lane >> 2;
    const int t    = lane & 3;
    const int qt   = (int)(gridDim.x - 1u - blockIdx.x);
    const int h    = blockIdx.y;
    const int b    = blockIdx.z;

    const size_t base = (size_t)b * TT * (3 * D_MODEL);
    const int    hcol = h * DH;
    const int    q0   = qt * 64 + w * 16;

    uint32_t qf[4][4];
    {
        const __half2 sc = __half2half2(__float2half(0.125f));
        const __half* qA = g_qkv + base + (size_t)(q0 + g) * (3 * D_MODEL) + hcol;
        const __half* qB = qA + (size_t)8 * (3 * D_MODEL);
        #pragma unroll
        for (int ks = 0; ks < 4; ks++) {
            int d = 16 * ks + 2 * t;
            __half2 v0 = __hmul2(*(const __half2*)(qA + d), sc);
            __half2 v1 = __hmul2(*(const __half2*)(qB + d), sc);
            __half2 v2 = __hmul2(*(const __half2*)(qA + d + 8), sc);
            __half2 v3 = __hmul2(*(const __half2*)(qB + d + 8), sc);
            qf[ks][0] = *(uint32_t*)&v0;
            qf[ks][1] = *(uint32_t*)&v1;
            qf[ks][2] = *(uint32_t*)&v2;
            qf[ks][3] = *(uint32_t*)&v3;
        }
    }

    float m0v = -1e30f, m1v = -1e30f, l0 = 0.f, l1 = 0.f;
    float o[8][4];
    #pragma unroll
    for (int nt = 0; nt < 8; nt++)
        #pragma unroll
        for (int e = 0; e < 4; e++) o[nt][e] = 0.f;

    for (int j = 0; j <= qt; j++) {
        __syncthreads();
        const __half* kp0 = g_qkv + base + (size_t)(j * 64) * (3 * D_MODEL)
                            + D_MODEL + hcol;
        #pragma unroll
        for (int it = 0; it < 8; it++) {
            int key = (tid & 7) + 8 * it;
            int c   = tid >> 3;
            uint2 wv = *(const uint2*)(kp0 + (size_t)key * (3 * D_MODEL) + c * 4);
            int idx = ((((key >> 3) * 4 + (c >> 2)) * 2 + ((c >> 1) & 1)) << 5)
                      + 4 * (key & 7) + 2 * (c & 1);
            *(uint2*)&Ks[idx] = wv;
        }
        #pragma unroll
        for (int it = 0; it < 4; it++) {
            int kpair = (tid >> 4) + 8 * it;
            int c     = tid & 15;
            const __half* va = kp0 + (size_t)(2 * kpair) * (3 * D_MODEL) + D_MODEL + c * 4;
            uint2 A2 = *(const uint2*)va;
            uint2 B2 = *(const uint2*)(va + 3 * D_MODEL);
            uint4 wv = make_uint4(__byte_perm(A2.x, B2.x, 0x5410),
                                  __byte_perm(A2.x, B2.x, 0x7632),
                                  __byte_perm(A2.y, B2.y, 0x5410),
                                  __byte_perm(A2.y, B2.y, 0x7632));
            *(uint4*)&Vs[kpair * 64 + ((4 * c) ^ (8 * (kpair & 3)))] = wv;
        }
        __syncthreads();

        const bool diag = (j == qt);
        const int  lim  = diag ? (2 * w + 2) : 8;

        float s[8][4];
        #pragma unroll
        for (int nt = 0; nt < 8; nt++) {
            if (nt < lim) {
                #pragma unroll
                for (int e = 0; e < 4; e++) s[nt][e] = 0.f;
                #pragma unroll
                for (int ks = 0; ks < 4; ks++) {
                    int kb = ((nt * 4 + ks) * 2) << 5;
                    int pos = 4 * g + t;
                    uint32_t bf[2] = {Ks[kb + pos], Ks[kb + 32 + pos]};
                    mma_fp16(s[nt], qf[ks], bf);
                }
            }
        }

        if (diag) {
            #pragma unroll
            for (int nt = 0; nt < 8; nt++) {
                if (nt < lim) {
                    #pragma unroll
                    for (int e = 0; e < 4; e++) {
                        int keyl = nt * 8 + 2 * t + (e & 1);
                        int rowl = w * 16 + g + ((e >> 1) << 3);
                        if (keyl > rowl) s[nt][e] = -1e30f;
                    }
                }
            }
        }

        float rm0 = -1e30f, rm1 = -1e30f;
        #pragma unroll
        for (int nt = 0; nt < 8; nt++) {
            if (nt < lim) {
                rm0 = fmaxf(rm0, fmaxf(s[nt][0], s[nt][1]));
                rm1 = fmaxf(rm1, fmaxf(s[nt][2], s[nt][3]));
            }
        }
        rm0 = fmaxf(rm0, __shfl_xor_sync(0xffffffffu, rm0, 1));
        rm0 = fmaxf(rm0, __shfl_xor_sync(0xffffffffu, rm0, 2));
        rm1 = fmaxf(rm1, __shfl_xor_sync(0xffffffffu, rm1, 1));
        rm1 = fmaxf(rm1, __shfl_xor_sync(0xffffffffu, rm1, 2));

        float mn0 = fmaxf(m0v, rm0), mn1 = fmaxf(m1v, rm1);
        float a0 = __expf(m0v - mn0), a1 = __expf(m1v - mn1);
        m0v = mn0; m1v = mn1;

        float rs0 = 0.f, rs1 = 0.f;
        #pragma unroll
        for (int nt = 0; nt < 8; nt++) {
            if (nt < lim) {
                s[nt][0] = __expf(s[nt][0] - mn0);
                s[nt][1] = __expf(s[nt][1] - mn0);
                s[nt][2] = __expf(s[nt][2] - mn1);
                s[nt][3] = __expf(s[nt][3] - mn1);
                rs0 += s[nt][0] + s[nt][1];
                rs1 += s[nt][2] + s[nt][3];
            }
        }
        rs0 += __shfl_xor_sync(0xffffffffu, rs0, 1);
        rs0 += __shfl_xor_sync(0xffffffffu, rs0, 2);
        rs1 += __shfl_xor_sync(0xffffffffu, rs1, 1);
        rs1 += __shfl_xor_sync(0xffffffffu, rs1, 2);
        l0 = l0 * a0 + rs0;
        l1 = l1 * a1 + rs1;

        #pragma unroll
        for (int nt = 0; nt < 8; nt++) {
            o[nt][0] *= a0; o[nt][1] *= a0;
            o[nt][2] *= a1; o[nt][3] *= a1;
        }

        const int limKK = lim >> 1;
        #pragma unroll
        for (int kk = 0; kk < 4; kk++) {
            if (kk < limKK) {
                uint32_t pA[4];
                pA[0] = pk(s[2 * kk][0],     s[2 * kk][1]);
                pA[1] = pk(s[2 * kk][2],     s[2 * kk][3]);
                pA[2] = pk(s[2 * kk + 1][0], s[2 * kk + 1][1]);
                pA[3] = pk(s[2 * kk + 1][2], s[2 * kk + 1][3]);

                const int r0w = (8 * kk + t) * 64;
                const int r1w = (8 * kk + t + 4) * 64;
                const int swz = 8 * t;
                #pragma unroll
                for (int nt = 0; nt < 8; nt++) {
                    int d = 8 * nt + g;
                    uint32_t bf[2] = {Vs[r0w + (d ^ swz)], Vs[r1w + (d ^ swz)]};
                    mma_fp16(o[nt], pA, bf);
                }
            }
        }
    }

    float inv0 = 1.f / l0, inv1 = 1.f / l1;
    size_t r0 = (size_t)(b * TT + q0 + g) * D_MODEL + hcol;
    size_t r1 = (size_t)(b * TT + q0 + g + 8) * D_MODEL + hcol;
    #pragma unroll
    for (int nt = 0; nt < 8; nt++) {
        int cb = nt * 8 + 2 * t;
        *(uint32_t*)&g_y[r0 + cb] = pk(o[nt][0] * inv0, o[nt][1] * inv0);
        *(uint32_t*)&g_y[r1 + cb] = pk(o[nt][2] * inv1, o[nt][3] * inv1);
    }
}

// ---------------------------------------------------------------------------
extern "C" void kernel_launch(void* const* d_in, const int* in_sizes, int n_in,
                              void* d_out, int out_size) {
    const float* x      = (const float*)d_in[0];
    const float* w_qkv  = (const float*)d_in[1];
    const float* w_proj = (const float*)d_in[2];
    float*       out    = (float*)d_out;

    __half *qkv_p, *y_p, *x_p, *wq_p, *wp_p;
    cudaGetSymbolAddress((void**)&qkv_p, g_qkv);
    cudaGetSymbolAddress((void**)&y_p,   g_y);
    cudaGetSymbolAddress((void**)&x_p,   g_x);
    cudaGetSymbolAddress((void**)&wq_p,  g_wq);
    cudaGetSymbolAddress((void**)&wp_p,  g_wp);

    f2h<<<(BT * D_MODEL) / 1024, 256>>>(x, x_p);
    f2h<<<(3 * D_MODEL * D_MODEL) / 1024, 256>>>(w_qkv, wq_p);
    f2h<<<(D_MODEL * D_MODEL) / 1024, 256>>>(w_proj, wp_p);

    gemm_fp16<__half>
        <<<dim3(3 * D_MODEL / 128, BT / 128), 256>>>(x_p, wq_p, qkv_p,
                                                     BT, 3 * D_MODEL, D_MODEL);

    attn_fp16<<<dim3(TT / 64, NH, BB), 128>>>();

    gemm_fp16<float>
        <<<dim3(D_MODEL / 128, BT / 128), 256>>>(y_p, wp_p, out,
                                                 BT, D_MODEL, D_MODEL);
}